// round 15
// baseline (speedup 1.0000x reference)
#include <cuda_runtime.h>
#include <cuda_bf16.h>
#include <cstdint>

#define KCODES 512
#define DDIM 64
#define HW 4096
#define MPTS 262144
#define ZQ_ELEMS 16777216
#define TPB 128                  // 4 warps; each warp owns 64 points (4 m-tiles)
#define TILEPTS 256
#define NTILES (MPTS / TILEPTS)  // 1024 tiles
#define NPERS 296                // persistent CTAs (148 SMs * 2)

// smem layout (bytes)
#define SM_ESQ 0                 // 512 f32                     [0,2048)
#define SM_THR 2048              // 256 f32                     [2048,3072)
#define SM_CNT 3072              // 256 u32                     [3072,4096)
#define SM_CAND 4096             // 256 * 16 u16 = 8192         [4096,12288)
#define SM_A 12288               // 256 rows * 128B bf16 z tile [12288,45056)
#define SM_BAL SM_A              // ballots overlay: 4 warps * 4KB = 16KB
#define SM_B 45056               // 512 rows * 128B bf16 codebook [45056,110592)
#define SM_TILE 110592           // tile ticket broadcast (u32)
#define SM_TOTAL 110720          // ~108.1 KB -> 2 CTAs/SM

#define TAU 1.0e-3f
#define CAND_MAX 16

__device__ double g_loss_sum;
__device__ unsigned g_ctr;
__device__ unsigned g_ticket;
__device__ float g_esq[KCODES];
__device__ __align__(16) __nv_bfloat16 g_embbf[KCODES * DDIM];

// ---- prep: e_sq (exact sequential fp32) + bf16 codebook ----
__global__ void vq_prep(const float* __restrict__ emb) {
    int k = threadIdx.x;                     // 512 threads
    const float* row = emb + k * DDIM;
    float q = 0.f;
    #pragma unroll
    for (int d = 0; d < DDIM; d++) {
        float v = row[d];
        q = __fadd_rn(q, __fmul_rn(v, v));
        g_embbf[k * DDIM + d] = __float2bfloat16(v);
    }
    g_esq[k] = q;
    if (k == 0) { g_loss_sum = 0.0; g_ctr = 0u; g_ticket = 0u; }
}

// ---- helpers ----
__device__ __forceinline__ uint32_t smem_u32(const void* p) {
    uint32_t a;
    asm("{ .reg .u64 t; cvta.to.shared.u64 t, %1; cvt.u32.u64 %0, t; }"
        : "=r"(a) : "l"(p));
    return a;
}
__device__ __forceinline__ uint32_t bf16x2(float a, float b) {  // lo=a, hi=b
    uint32_t r;
    asm("cvt.rn.bf16x2.f32 %0, %1, %2;" : "=r"(r) : "f"(b), "f"(a));
    return r;
}
__device__ __forceinline__ void ldsm_x4(uint32_t addr, uint32_t& r0, uint32_t& r1,
                                        uint32_t& r2, uint32_t& r3) {
    asm volatile("ldmatrix.sync.aligned.m8n8.x4.shared.b16 {%0,%1,%2,%3}, [%4];"
                 : "=r"(r0), "=r"(r1), "=r"(r2), "=r"(r3) : "r"(addr));
}
__device__ __forceinline__ void mma_bf16(float& d0, float& d1, float& d2, float& d3,
                                         uint32_t a0, uint32_t a1, uint32_t a2, uint32_t a3,
                                         uint32_t b0, uint32_t b1) {
    asm volatile(
        "mma.sync.aligned.m16n8k16.row.col.f32.bf16.bf16.f32 "
        "{%0,%1,%2,%3}, {%4,%5,%6,%7}, {%8,%9}, {%0,%1,%2,%3};"
        : "+f"(d0), "+f"(d1), "+f"(d2), "+f"(d3)
        : "r"(a0), "r"(a1), "r"(a2), "r"(a3), "r"(b0), "r"(b1));
}
__device__ __forceinline__ float exact_dist(float S, float esq, float dot) {
    return __fsub_rn(__fadd_rn(S, esq), __fmul_rn(2.0f, dot));
}

__global__ __launch_bounds__(TPB, 2)
void vq_main(const float* __restrict__ z, const float* __restrict__ emb,
             float* __restrict__ out) {
    extern __shared__ char smem[];
    const uint32_t sb = smem_u32(smem);
    const int tid = threadIdx.x;
    const int lane = tid & 31, wid = tid >> 5;      // 4 warps
    const int g = lane >> 2, t = lane & 3;
    const int wbase = wid * 64;                     // 64 point-rows per warp

    float* sm_esq = (float*)(smem + SM_ESQ);
    float* sm_thr = (float*)(smem + SM_THR);
    unsigned* sm_cnt = (unsigned*)(smem + SM_CNT);
    uint16_t* sm_cand = (uint16_t*)(smem + SM_CAND);
    volatile unsigned* sm_tile = (volatile unsigned*)(smem + SM_TILE);

    // One-time: e_sq + B tile (codebook) into smem
    for (int i = tid; i < KCODES; i += TPB) sm_esq[i] = g_esq[i];
    {
        const uint4* gb = (const uint4*)g_embbf;
        #pragma unroll 4
        for (int it = 0; it < 32; it++) {
            uint32_t i16 = (uint32_t)(it * TPB + tid);
            uint4 v = gb[i16];
            uint32_t row = i16 >> 3, j = i16 & 7;
            uint32_t a = sb + SM_B + row * 128 + ((j ^ (row & 7)) << 4);
            asm volatile("st.shared.v4.b32 [%0], {%1,%2,%3,%4};"
                         :: "r"(a), "r"(v.x), "r"(v.y), "r"(v.z), "r"(v.w) : "memory");
        }
    }

    const int brow = lane & 7;
    const int bsub = lane >> 3;
    const float INF = __int_as_float(0x7f800000);
    const uint32_t balbase = sb + SM_BAL + (uint32_t)wid * 4096;
    double lsum_run = 0.0;                          // per-thread loss across tiles

    for (;;) {
        if (tid == 0) *sm_tile = atomicAdd(&g_ticket, 1u);
        sm_cnt[tid] = 0u;
        sm_cnt[tid + 128] = 0u;
        __syncthreads();
        const int tile = (int)*sm_tile;
        if (tile >= NTILES) break;

        const int pbase = tile * TILEPTS;
        const int n = pbase >> 12;                  // constant within tile (256 | 4096)
        const int hw0 = (pbase & (HW - 1)) + tid;   // point rows tid and tid+128
        const float* zb = z + (size_t)n * (DDIM * HW);

        // Phase A: 2 points/thread -> z_sq (sequential fp32) + bf16 A tile
        float S0 = 0.f, S1 = 0.f;
        #pragma unroll 1
        for (int pt = 0; pt < 2; pt++) {
            const float* zp = zb + hw0 + pt * 128;
            const int arow = tid + pt * 128;
            float Sx = 0.f;
            #pragma unroll
            for (int j = 0; j < 8; j++) {
                float v[8];
                #pragma unroll
                for (int e = 0; e < 8; e++) v[e] = zp[(8 * j + e) * HW];
                #pragma unroll
                for (int e = 0; e < 8; e++) Sx = __fadd_rn(Sx, __fmul_rn(v[e], v[e]));
                uint32_t w0 = bf16x2(v[0], v[1]);
                uint32_t w1 = bf16x2(v[2], v[3]);
                uint32_t w2 = bf16x2(v[4], v[5]);
                uint32_t w3 = bf16x2(v[6], v[7]);
                uint32_t a = sb + SM_A + (uint32_t)arow * 128
                           + (uint32_t)((j ^ (arow & 7)) << 4);
                asm volatile("st.shared.v4.b32 [%0], {%1,%2,%3,%4};"
                             :: "r"(a), "r"(w0), "r"(w1), "r"(w2), "r"(w3) : "memory");
            }
            if (pt == 0) S0 = Sx; else S1 = Sx;
        }
        __syncthreads();

        // A fragments: 4 m-tiles x 4 k-steps
        uint32_t afr[4][4][4];
        {
            const int sub = lane >> 3;
            const int rowo = (lane & 7) + ((sub & 1) << 3);
            #pragma unroll
            for (int m = 0; m < 4; m++) {
                #pragma unroll
                for (int kc = 0; kc < 4; kc++) {
                    int row = wbase + 16 * m + rowo;
                    int gran = 2 * kc + (sub >> 1);
                    uint32_t a = sb + SM_A + (uint32_t)row * 128
                               + (uint32_t)((gran ^ (row & 7)) << 4);
                    ldsm_x4(a, afr[m][kc][0], afr[m][kc][1], afr[m][kc][2], afr[m][kc][3]);
                }
            }
        }

        // Pass 1: MMA sweep, per-fragment-row min (8 rows/thread)
        float mn[8];
        #pragma unroll
        for (int r = 0; r < 8; r++) mn[r] = INF;
        #pragma unroll 2
        for (int nt = 0; nt < 64; nt++) {
            uint32_t b[8];
            #pragma unroll
            for (int kk = 0; kk < 2; kk++) {
                int row = nt * 8 + brow;
                int gran = 4 * kk + bsub;
                uint32_t a = sb + SM_B + (uint32_t)row * 128
                           + (uint32_t)((gran ^ (row & 7)) << 4);
                ldsm_x4(a, b[4*kk], b[4*kk+1], b[4*kk+2], b[4*kk+3]);
            }
            float2 e2 = *(const float2*)(sm_esq + nt * 8 + 2 * t);
            #pragma unroll
            for (int m = 0; m < 4; m++) {
                float dA0 = 0.f, dA1 = 0.f, dA2 = 0.f, dA3 = 0.f;
                float dB0 = 0.f, dB1 = 0.f, dB2 = 0.f, dB3 = 0.f;
                mma_bf16(dA0, dA1, dA2, dA3, afr[m][0][0], afr[m][0][1], afr[m][0][2], afr[m][0][3], b[0], b[1]);
                mma_bf16(dB0, dB1, dB2, dB3, afr[m][1][0], afr[m][1][1], afr[m][1][2], afr[m][1][3], b[2], b[3]);
                mma_bf16(dA0, dA1, dA2, dA3, afr[m][2][0], afr[m][2][1], afr[m][2][2], afr[m][2][3], b[4], b[5]);
                mma_bf16(dB0, dB1, dB2, dB3, afr[m][3][0], afr[m][3][1], afr[m][3][2], afr[m][3][3], b[6], b[7]);
                float s0 = fmaf(-2.f, dA0 + dB0, e2.x);
                float s1 = fmaf(-2.f, dA1 + dB1, e2.y);
                float s2 = fmaf(-2.f, dA2 + dB2, e2.x);
                float s3 = fmaf(-2.f, dA3 + dB3, e2.y);
                mn[2*m]   = fminf(mn[2*m],   fminf(s0, s1));
                mn[2*m+1] = fminf(mn[2*m+1], fminf(s2, s3));
            }
        }
        #pragma unroll
        for (int r = 0; r < 8; r++) {
            #pragma unroll
            for (int off = 1; off <= 2; off <<= 1)
                mn[r] = fminf(mn[r], __shfl_xor_sync(0xffffffffu, mn[r], off));
        }
        if (t == 0) {
            #pragma unroll
            for (int m = 0; m < 4; m++) {
                sm_thr[wbase + 16 * m + g]     = mn[2*m]   + TAU;
                sm_thr[wbase + 16 * m + 8 + g] = mn[2*m+1] + TAU;
            }
        }
        __syncthreads();   // fences A-frag reads before SM_BAL overlay writes

        float thrR[8];
        #pragma unroll
        for (int m = 0; m < 4; m++) {
            thrR[2*m]   = sm_thr[wbase + 16 * m + g];
            thrR[2*m+1] = sm_thr[wbase + 16 * m + 8 + g];
        }

        // Pass 2: identical MMA sweep; ballot capture (16 words/nt/warp)
        #pragma unroll 2
        for (int nt = 0; nt < 64; nt++) {
            uint32_t b[8];
            #pragma unroll
            for (int kk = 0; kk < 2; kk++) {
                int row = nt * 8 + brow;
                int gran = 4 * kk + bsub;
                uint32_t a = sb + SM_B + (uint32_t)row * 128
                           + (uint32_t)((gran ^ (row & 7)) << 4);
                ldsm_x4(a, b[4*kk], b[4*kk+1], b[4*kk+2], b[4*kk+3]);
            }
            float2 e2 = *(const float2*)(sm_esq + nt * 8 + 2 * t);
            uint32_t bal[16];
            #pragma unroll
            for (int m = 0; m < 4; m++) {
                float dA0 = 0.f, dA1 = 0.f, dA2 = 0.f, dA3 = 0.f;
                float dB0 = 0.f, dB1 = 0.f, dB2 = 0.f, dB3 = 0.f;
                mma_bf16(dA0, dA1, dA2, dA3, afr[m][0][0], afr[m][0][1], afr[m][0][2], afr[m][0][3], b[0], b[1]);
                mma_bf16(dB0, dB1, dB2, dB3, afr[m][1][0], afr[m][1][1], afr[m][1][2], afr[m][1][3], b[2], b[3]);
                mma_bf16(dA0, dA1, dA2, dA3, afr[m][2][0], afr[m][2][1], afr[m][2][2], afr[m][2][3], b[4], b[5]);
                mma_bf16(dB0, dB1, dB2, dB3, afr[m][3][0], afr[m][3][1], afr[m][3][2], afr[m][3][3], b[6], b[7]);
                float s0 = fmaf(-2.f, dA0 + dB0, e2.x);
                float s1 = fmaf(-2.f, dA1 + dB1, e2.y);
                float s2 = fmaf(-2.f, dA2 + dB2, e2.x);
                float s3 = fmaf(-2.f, dA3 + dB3, e2.y);
                bal[4*m + 0] = __ballot_sync(0xffffffffu, s0 < thrR[2*m]);
                bal[4*m + 1] = __ballot_sync(0xffffffffu, s1 < thrR[2*m]);
                bal[4*m + 2] = __ballot_sync(0xffffffffu, s2 < thrR[2*m+1]);
                bal[4*m + 3] = __ballot_sync(0xffffffffu, s3 < thrR[2*m+1]);
            }
            uint32_t a0 = balbase + (uint32_t)nt * 64;
            asm volatile(
                "{\n\t.reg .pred p;\n\tsetp.eq.u32 p, %0, 0;\n\t"
                "@p st.shared.v4.b32 [%1], {%2,%3,%4,%5};\n\t"
                "@p st.shared.v4.b32 [%6], {%7,%8,%9,%10};\n\t"
                "@p st.shared.v4.b32 [%11], {%12,%13,%14,%15};\n\t"
                "@p st.shared.v4.b32 [%16], {%17,%18,%19,%20};\n\t}"
                :: "r"(lane),
                   "r"(a0),      "r"(bal[0]),  "r"(bal[1]),  "r"(bal[2]),  "r"(bal[3]),
                   "r"(a0 + 16), "r"(bal[4]),  "r"(bal[5]),  "r"(bal[6]),  "r"(bal[7]),
                   "r"(a0 + 32), "r"(bal[8]),  "r"(bal[9]),  "r"(bal[10]), "r"(bal[11]),
                   "r"(a0 + 48), "r"(bal[12]), "r"(bal[13]), "r"(bal[14]), "r"(bal[15])
                : "memory");
        }
        __syncwarp();

        // Decode ballots -> candidate lists (1024 words / 32 lanes = 32 iters)
        #pragma unroll 1
        for (int w = 0; w < 32; w++) {
            int word = lane + 32 * w;
            uint32_t bits;
            asm volatile("ld.shared.b32 %0, [%1];"
                         : "=r"(bits) : "r"(balbase + (uint32_t)word * 4));
            if (bits) {
                int nt = word >> 4, slot = word & 15;
                int m = slot >> 2, hi = (slot >> 1) & 1, c01 = slot & 1;
                do {
                    int bpos = __ffs(bits) - 1; bits &= bits - 1;
                    int bt = bpos & 3, bg = bpos >> 2;
                    int row = wbase + 16 * m + 8 * hi + bg;
                    int k = nt * 8 + 2 * bt + c01;
                    unsigned ix = atomicAdd(&sm_cnt[row], 1u);
                    if (ix < (unsigned)CAND_MAX) sm_cand[row * CAND_MAX + ix] = (uint16_t)k;
                } while (bits);
            }
        }
        __syncthreads();

        // Epilogue: 2 points per thread
        float lsum = 0.f;
        #pragma unroll 1
        for (int pt = 0; pt < 2; pt++) {
            const int row = tid + pt * 128;
            const int p = pbase + row;
            const float* zp = zb + hw0 + pt * 128;
            const float S = pt ? S1 : S0;

            const unsigned cnt = sm_cnt[row];
            int bestk;
            if (cnt == 1u) {
                bestk = (int)sm_cand[row * CAND_MAX];
            } else if (cnt <= (unsigned)CAND_MAX) {
                float bestd = INF; bestk = KCODES;
                for (unsigned c = 0; c < cnt; c++) {
                    int k = (int)sm_cand[row * CAND_MAX + c];
                    const float* er = emb + k * DDIM;
                    float dot = 0.f;
                    #pragma unroll 2
                    for (int j = 0; j < 8; j++) {
                        float zc[8];
                        #pragma unroll
                        for (int e = 0; e < 8; e++) zc[e] = zp[(8 * j + e) * HW];
                        #pragma unroll
                        for (int e = 0; e < 8; e++)
                            dot = __fmaf_rn(zc[e], er[8 * j + e], dot);
                    }
                    float dist = exact_dist(S, sm_esq[k], dot);
                    if (dist < bestd || (dist == bestd && k < bestk)) { bestd = dist; bestk = k; }
                }
            } else {
                // fallback (P ~ 1e-12): exact full scan, ascending k, strict <
                float bestd = INF; bestk = 0;
                for (int k0 = 0; k0 < KCODES; k0 += 8) {
                    float dot[8];
                    #pragma unroll
                    for (int c = 0; c < 8; c++) dot[c] = 0.f;
                    #pragma unroll 1
                    for (int j = 0; j < 8; j++) {
                        float zc[8];
                        #pragma unroll
                        for (int e = 0; e < 8; e++) zc[e] = zp[(8 * j + e) * HW];
                        #pragma unroll
                        for (int c = 0; c < 8; c++) {
                            const float* er = emb + (k0 + c) * DDIM + 8 * j;
                            #pragma unroll
                            for (int e = 0; e < 8; e++)
                                dot[c] = __fmaf_rn(zc[e], er[e], dot[c]);
                        }
                    }
                    #pragma unroll
                    for (int c = 0; c < 8; c++) {
                        float dist = exact_dist(S, sm_esq[k0 + c], dot[c]);
                        if (dist < bestd) { bestd = dist; bestk = k0 + c; }
                    }
                }
            }

            // Output: z_q (straight-through), loss, index
            const float* er = emb + bestk * DDIM;
            float* outz = out + (size_t)n * (DDIM * HW) + hw0 + pt * 128;
            #pragma unroll 2
            for (int j = 0; j < 8; j++) {
                float zc[8], ec[8];
                #pragma unroll
                for (int e = 0; e < 8; e++) zc[e] = zp[(8 * j + e) * HW];
                #pragma unroll
                for (int e = 0; e < 8; e++) ec[e] = er[8 * j + e];
                #pragma unroll
                for (int e = 0; e < 8; e++) {
                    float v = zc[e], q = ec[e];
                    outz[(8 * j + e) * HW] = __fadd_rn(v, __fsub_rn(q, v));
                    float x = __fsub_rn(v, q);
                    lsum = __fmaf_rn(x, x, lsum);
                }
            }
            out[ZQ_ELEMS + 1 + p] = (float)bestk;
        }
        lsum_run += (double)lsum;
    }

    // loss: warp-reduce the per-thread running sums, one atomic per warp
    #pragma unroll
    for (int off = 16; off > 0; off >>= 1)
        lsum_run += __shfl_down_sync(0xffffffffu, lsum_run, off);
    if (lane == 0) atomicAdd(&g_loss_sum, lsum_run);

    __threadfence();
    __syncthreads();
    if (tid == 0) {
        unsigned tk = atomicAdd(&g_ctr, 1u);
        if (tk == (unsigned)(NPERS - 1)) {
            double s = atomicAdd(&g_loss_sum, 0.0);
            out[ZQ_ELEMS] = (float)(s / (double)ZQ_ELEMS);
        }
    }
}

extern "C" void kernel_launch(void* const* d_in, const int* in_sizes, int n_in,
                              void* d_out, int out_size) {
    const float* z   = (const float*)d_in[0];   // z_e (64,64,64,64) f32
    const float* emb = (const float*)d_in[1];   // emb_weight (512,64) f32
    float* out = (float*)d_out;

    cudaFuncSetAttribute(vq_main, cudaFuncAttributeMaxDynamicSharedMemorySize, SM_TOTAL);
    vq_prep<<<1, KCODES>>>(emb);
    vq_main<<<NPERS, TPB, SM_TOTAL>>>(z, emb, out);
}